// round 16
// baseline (speedup 1.0000x reference)
#include <cuda_runtime.h>
#include <cuda_bf16.h>
#include <cuda_fp16.h>
#include <math.h>
#include <stdint.h>

// Problem constants
constexpr int BATCH = 2;
constexpr int SEQ   = 2048;
constexpr int DM    = 2048;
constexpr int NH    = 16;
constexpr int NKV   = 4;
constexpr int HDIM  = 128;
constexpr int HHALF = 64;
constexpr float EPSV = 1e-6f;
constexpr float SCL_LOG2 = 0.12754245006483662f; // 1/sqrt(128) * log2(e)
constexpr int MR  = BATCH * SEQ;                  // 4096 rows
constexpr int KVD = NKV * HDIM;                   // 512

// ---------------- scratch (device globals — no runtime allocation) --------
__device__ float g_Qp[MR * DM];                   // Q projection fp32 (accumulated)
__device__ float g_Kp[MR * KVD];                  // K projection fp32 (accumulated)
__device__ __half g_Qh[MR * DM];                  // Q after norm+rope (pre-scaled), fp16
__device__ __half g_Kh[MR * KVD];                 // K after norm+rope, fp16
__device__ __half g_Vh[MR * KVD];                 // V projection, fp16 (accumulated)

__device__ __half g_Aq_h[MR * DM],  g_Aq_l[MR * DM];     // fp16 hi/lo activations
__device__ __half g_Akv_h[MR * DM], g_Akv_l[MR * DM];
__device__ __half g_Ao_h[MR * DM],  g_Ao_l[MR * DM];     // attn out hi/lo
__device__ __half g_WqT[DM * DM];                         // fp16 weights (transposed)
__device__ __half g_WkvT[2 * KVD * DM];                   // K rows 0-511, V rows 512-1023
__device__ __half g_WoT[DM * DM];

// ---------------------------------------------------------------------------
// Helpers (baseline PTX only: cp.async, ldmatrix, mma.sync)
// ---------------------------------------------------------------------------
__device__ __forceinline__ uint32_t smem_u32(const void* p) {
    uint32_t a;
    asm("{ .reg .u64 t; cvta.to.shared.u64 t, %1; cvt.u32.u64 %0, t; }"
        : "=r"(a) : "l"(p));
    return a;
}

__device__ __forceinline__ void cp16(uint32_t dst, const void* src) {
    asm volatile("cp.async.cg.shared.global [%0], [%1], 16;" :: "r"(dst), "l"(src));
}
__device__ __forceinline__ void cp_commit() {
    asm volatile("cp.async.commit_group;" ::: "memory");
}
template <int N>
__device__ __forceinline__ void cp_wait() {
    asm volatile("cp.async.wait_group %0;" :: "n"(N) : "memory");
}

__device__ __forceinline__ float ex2(float x) {
    float y;
    asm("ex2.approx.f32 %0, %1;" : "=f"(y) : "f"(x));
    return y;
}

__device__ __forceinline__ void ldsm4(uint32_t& r0, uint32_t& r1, uint32_t& r2,
                                      uint32_t& r3, uint32_t addr) {
    asm volatile("ldmatrix.sync.aligned.m8n8.x4.shared.b16 {%0,%1,%2,%3}, [%4];"
                 : "=r"(r0), "=r"(r1), "=r"(r2), "=r"(r3) : "r"(addr));
}
__device__ __forceinline__ void ldsm4t(uint32_t& r0, uint32_t& r1, uint32_t& r2,
                                       uint32_t& r3, uint32_t addr) {
    asm volatile("ldmatrix.sync.aligned.m8n8.x4.trans.shared.b16 {%0,%1,%2,%3}, [%4];"
                 : "=r"(r0), "=r"(r1), "=r"(r2), "=r"(r3) : "r"(addr));
}

__device__ __forceinline__ void mma_fp16(float* c, const uint32_t* a,
                                         uint32_t b0, uint32_t b1) {
    asm volatile(
        "mma.sync.aligned.m16n8k16.row.col.f32.f16.f16.f32 "
        "{%0,%1,%2,%3}, {%4,%5,%6,%7}, {%8,%9}, {%0,%1,%2,%3};"
        : "+f"(c[0]), "+f"(c[1]), "+f"(c[2]), "+f"(c[3])
        : "r"(a[0]), "r"(a[1]), "r"(a[2]), "r"(a[3]), "r"(b0), "r"(b1));
}

// ---------------------------------------------------------------------------
// Zero-init of the accumulated projection buffers (float4-wide)
// ---------------------------------------------------------------------------
constexpr int ZQ4 = MR * DM / 4;
constexpr int ZK4 = MR * KVD / 4;
constexpr int ZV4 = MR * KVD / 8;
constexpr int ZTOT = ZQ4 + ZK4 + ZV4;

__global__ __launch_bounds__(256) void zero_qkv(
    float* __restrict__ Qp, float* __restrict__ Kp, __half* __restrict__ Vh)
{
    int i = blockIdx.x * blockDim.x + threadIdx.x;
    if (i >= ZTOT) return;
    const float4 z = make_float4(0.f, 0.f, 0.f, 0.f);
    if (i < ZQ4)            ((float4*)Qp)[i] = z;
    else if (i < ZQ4 + ZK4) ((float4*)Kp)[i - ZQ4] = z;
    else                    ((float4*)Vh)[i - ZQ4 - ZK4] = z;
}

// ---------------------------------------------------------------------------
// fp16 hi/lo split for BOTH activation tensors in one launch.
// ---------------------------------------------------------------------------
__global__ __launch_bounds__(256) void split_rows2(
    const float* __restrict__ X1, __half* __restrict__ H1, __half* __restrict__ L1,
    const float* __restrict__ X2, __half* __restrict__ H2, __half* __restrict__ L2,
    int n4)
{
    int i = blockIdx.x * blockDim.x + threadIdx.x;
    const float* X;
    __half *Hh, *Ll;
    if (i < n4) { X = X1; Hh = H1; Ll = L1; }
    else        { X = X2; Hh = H2; Ll = L2; i -= n4; }

    float4 v = ((const float4*)X)[i];
    __half h0 = __float2half(v.x);
    __half h1 = __float2half(v.y);
    __half h2 = __float2half(v.z);
    __half h3 = __float2half(v.w);
    __half2* Hp = (__half2*)Hh;
    Hp[2 * i]     = __halves2half2(h0, h1);
    Hp[2 * i + 1] = __halves2half2(h2, h3);
    __half l0 = __float2half(v.x - __half2float(h0));
    __half l1 = __float2half(v.y - __half2float(h1));
    __half l2 = __float2half(v.z - __half2float(h2));
    __half l3 = __float2half(v.w - __half2float(h3));
    __half2* Lp = (__half2*)Ll;
    Lp[2 * i]     = __halves2half2(l0, l1);
    Lp[2 * i + 1] = __halves2half2(l2, l3);
}

// ---------------------------------------------------------------------------
// Transpose to fp16 for ALL FOUR weights in one launch.
// ---------------------------------------------------------------------------
__global__ __launch_bounds__(256) void split_transpose4(
    const float* __restrict__ Wq, const float* __restrict__ Wk,
    const float* __restrict__ Wv, const float* __restrict__ Wo,
    __half* __restrict__ WqT, __half* __restrict__ WkvT, __half* __restrict__ WoT)
{
    const int z = blockIdx.z;
    const float* W;
    __half* TH;
    int N;
    if (z == 0)      { W = Wq; TH = WqT; N = DM; }
    else if (z == 1) { W = Wk; TH = WkvT; N = KVD; }
    else if (z == 2) { W = Wv; TH = WkvT + (size_t)KVD * DM; N = KVD; }
    else             { W = Wo; TH = WoT; N = DM; }

    const int n0 = blockIdx.y * 32;
    if (n0 >= N) return;
    const int k0 = blockIdx.x * 32;

    __shared__ float tile[32][33];
    const int tx = threadIdx.x, ty = threadIdx.y;     // 32 x 8
#pragma unroll
    for (int i = 0; i < 4; i++)
        tile[ty + i * 8][tx] = W[(size_t)(k0 + ty + i * 8) * N + n0 + tx];
    __syncthreads();
#pragma unroll
    for (int i = 0; i < 4; i++) {
        float v = tile[tx][ty + i * 8];
        int n = n0 + ty + i * 8;
        TH[(size_t)n * DM + k0 + tx] = __float2half(v);
    }
}

// ---------------------------------------------------------------------------
// GEMM: CTA tile 256(M) x 128(N), BK=32, 8 warps in 4x2, warp tile 64x64.
// 4-stage cp.async pipeline, one __syncthreads per iteration, 1 CTA/SM.
// MAC/smem-byte = 1.5x the old 128x128/BK64 config (smem-BW bound fix).
// ---------------------------------------------------------------------------
constexpr int LDB    = 40;                  // padded halves per smem row (32+8)
constexpr int AB2    = 256 * LDB * 2;       // A tile bytes = 20480
constexpr int BB2    = 128 * LDB * 2;       // B tile bytes = 10240
constexpr int STAGE2 = AB2 + BB2;           // 30720 B
constexpr int NSTG2  = 4;
constexpr int GEMM_SMEM = NSTG2 * STAGE2;   // 122880 B (1 CTA/SM)

// 4-stage mainloop; A source switches A0 -> A1 at iteration 64.
template <int NIT>
__device__ __forceinline__ void gemm_mainloop256(
    uint32_t sb,
    const __half* __restrict__ A0, const __half* __restrict__ A1,
    const __half* __restrict__ Bg,
    int m0, int n0, float (&acc)[4][8][4])
{
    const int t = threadIdx.x, lane = t & 31, wid = t >> 5;
    const int wm = wid >> 1, wn = wid & 1;           // 4 x 2 warp grid

    auto load_stage = [&](int it, int s) {
        const __half* Ag = (it < 64) ? A0 : A1;
        const int koff = (it & 63) << 5;             // halves
        const uint32_t Ab = sb + s * STAGE2;
        const uint32_t Bb = Ab + AB2;
        // A: 256 rows x 64B; thread t -> row t, 4 chunks
#pragma unroll
        for (int c = 0; c < 4; c++)
            cp16(Ab + t * (LDB * 2) + c * 16,
                 Ag + (size_t)(m0 + t) * DM + koff + c * 8);
        // B: 128 rows x 64B; thread t -> row t>>1, 2 chunks
        const int br = t >> 1;
#pragma unroll
        for (int c = 0; c < 2; c++) {
            const int ch = (t & 1) * 2 + c;
            cp16(Bb + br * (LDB * 2) + ch * 16,
                 Bg + (size_t)(n0 + br) * DM + koff + ch * 8);
        }
        cp_commit();
    };

    // prologue: 3 stages in flight
    load_stage(0, 0);
    load_stage(1, 1);
    load_stage(2, 2);

    const uint32_t a_off = (uint32_t)((wm * 64 + (lane & 15)) * (LDB * 2) +
                                      ((lane >> 4) << 4));
    const uint32_t b_off = (uint32_t)((wn * 64 + ((lane >> 4) << 3) + (lane & 7)) * (LDB * 2) +
                                      (((lane >> 3) & 1) << 4));

    int stg = 0;
    for (int it = 0; it < NIT; it++) {
        cp_wait<2>();              // stage `it` resident (it+1, it+2 may fly)
        __syncthreads();           // stage `it` visible; slot (it+3)%4 free

        if (it + 3 < NIT) {
            const int s3 = (stg + 3 >= NSTG2) ? stg + 3 - NSTG2 : stg + 3;
            load_stage(it + 3, s3);
        } else {
            cp_commit();           // empty group keeps wait-count invariant
        }

        const uint32_t Ab = sb + stg * STAGE2;
        const uint32_t Bb = Ab + AB2;

#pragma unroll
        for (int ks = 0; ks < 2; ks++) {
            uint32_t a[4][4];
            uint32_t b[8][2];
#pragma unroll
            for (int i = 0; i < 4; i++)
                ldsm4(a[i][0], a[i][1], a[i][2], a[i][3],
                      Ab + a_off + i * 16 * (LDB * 2) + ks * 32);
#pragma unroll
            for (int j = 0; j < 4; j++) {
                uint32_t r0, r1, r2, r3;
                ldsm4(r0, r1, r2, r3,
                      Bb + b_off + j * 16 * (LDB * 2) + ks * 32);
                b[j * 2][0] = r0;     b[j * 2][1] = r1;
                b[j * 2 + 1][0] = r2; b[j * 2 + 1][1] = r3;
            }
#pragma unroll
            for (int i = 0; i < 4; i++)
#pragma unroll
                for (int j = 0; j < 8; j++)
                    mma_fp16(acc[i][j], a[i], b[j][0], b[j][1]);
        }

        stg = (stg + 1 >= NSTG2) ? 0 : stg + 1;
    }
}

// Wo projection: 128 iters (Ah for 0-63, Al for 64-127), fp32 direct store.
__global__ __launch_bounds__(256, 1) void gemm_wo(
    const __half* __restrict__ Ahi, const __half* __restrict__ Alo,
    const __half* __restrict__ Bg, float* __restrict__ Cf)
{
    extern __shared__ __align__(16) char smg[];
    const int m0 = blockIdx.y * 256, n0 = blockIdx.x * 128;
    float acc[4][8][4] = {};
    gemm_mainloop256<128>(smem_u32(smg), Ahi, Alo, Bg, m0, n0, acc);

    const int lane = threadIdx.x & 31, wid = threadIdx.x >> 5;
    const int wm = wid >> 1, wn = wid & 1;
#pragma unroll
    for (int i = 0; i < 4; i++) {
#pragma unroll
        for (int j = 0; j < 8; j++) {
            const int m = m0 + wm * 64 + i * 16 + (lane >> 2);
            const int n = n0 + wn * 64 + j * 8 + ((lane & 3) << 1);
            *(float2*)&Cf[(size_t)m * DM + n] =
                make_float2(acc[i][j][0], acc[i][j][1]);
            *(float2*)&Cf[(size_t)(m + 8) * DM + n] =
                make_float2(acc[i][j][2], acc[i][j][3]);
        }
    }
}

// Merged Q + KV projections, section-split (blockIdx.z = 0: Ah, 1: Al),
// 64 iters/CTA, accumulated into pre-zeroed outputs with atomics.
// blockIdx.x < 16: Q n-tile; >= 16: KV n-tile (n0<512 -> Kp; else -> Vh).
__global__ __launch_bounds__(256, 1) void gemm_qkv(
    const __half* __restrict__ Aqh, const __half* __restrict__ Aql,
    const __half* __restrict__ Akh, const __half* __restrict__ Akl,
    const __half* __restrict__ WqT, const __half* __restrict__ WkvT,
    float* __restrict__ Qp, float* __restrict__ Kp, __half* __restrict__ Vh)
{
    extern __shared__ __align__(16) char smg[];
    const bool isQ = (blockIdx.x < 16);
    const int n0 = (isQ ? blockIdx.x : blockIdx.x - 16) * 128;
    const int m0 = blockIdx.y * 256;
    const int sec = blockIdx.z;                    // 0: Ah*W, 1: Al*W

    const __half* Ag = (sec == 1) ? (isQ ? Aql : Akl) : (isQ ? Aqh : Akh);
    const __half* Bg = isQ ? WqT : WkvT;

    float acc[4][8][4] = {};
    gemm_mainloop256<64>(smem_u32(smg), Ag, Ag, Bg, m0, n0, acc);

    const int lane = threadIdx.x & 31, wid = threadIdx.x >> 5;
    const int wm = wid >> 1, wn = wid & 1;
    const bool isV = (!isQ) && (n0 >= KVD);

    if (!isV) {
        float* C = isQ ? Qp : Kp;
        const int W = isQ ? DM : KVD;
#pragma unroll
        for (int i = 0; i < 4; i++) {
#pragma unroll
            for (int j = 0; j < 8; j++) {
                const int m = m0 + wm * 64 + i * 16 + (lane >> 2);
                const int n = n0 + wn * 64 + j * 8 + ((lane & 3) << 1);
                atomicAdd(&C[(size_t)m * W + n],       acc[i][j][0]);
                atomicAdd(&C[(size_t)m * W + n + 1],   acc[i][j][1]);
                atomicAdd(&C[(size_t)(m + 8) * W + n],     acc[i][j][2]);
                atomicAdd(&C[(size_t)(m + 8) * W + n + 1], acc[i][j][3]);
            }
        }
    } else {
        const int nb = n0 - KVD;
#pragma unroll
        for (int i = 0; i < 4; i++) {
#pragma unroll
            for (int j = 0; j < 8; j++) {
                const int m = m0 + wm * 64 + i * 16 + (lane >> 2);
                const int n = nb + wn * 64 + j * 8 + ((lane & 3) << 1);
                atomicAdd((__half2*)&Vh[(size_t)m * KVD + n],
                          __floats2half2_rn(acc[i][j][0], acc[i][j][1]));
                atomicAdd((__half2*)&Vh[(size_t)(m + 8) * KVD + n],
                          __floats2half2_rn(acc[i][j][2], acc[i][j][3]));
            }
        }
    }
}

// ---------------------------------------------------------------------------
// Fused per-head RMSNorm + RoPE for BOTH Q and K in one launch.
// Q output pre-scaled by SM_SCALE*log2(e).
// ---------------------------------------------------------------------------
__global__ __launch_bounds__(256) void norm_rope_qk(
    const float* __restrict__ Qp, const float* __restrict__ Kp,
    const float* __restrict__ q_scale, const float* __restrict__ k_scale,
    const float* __restrict__ cs, const float* __restrict__ sn,
    __half* __restrict__ Qh, __half* __restrict__ Kh)
{
    int gw   = (int)((blockIdx.x * blockDim.x + threadIdx.x) >> 5);
    const int lane = threadIdx.x & 31;

    const float* P;
    const float* scale;
    __half* out;
    int nh;
    float oscale;
    if (gw < MR * NH) {
        P = Qp; scale = q_scale; out = Qh; nh = NH; oscale = SCL_LOG2;
    } else {
        gw -= MR * NH;
        P = Kp; scale = k_scale; out = Kh; nh = NKV; oscale = 1.0f;
    }

    const int h  = gw % nh;
    const int bt = gw / nh;
    const int tt = bt % SEQ;

    const size_t base = (size_t)bt * (nh * HDIM) + (size_t)h * HDIM;
    const int d = lane * 2;

    float2 lo = *(const float2*)&P[base + d];
    float2 hi = *(const float2*)&P[base + d + HHALF];

    float ss = lo.x * lo.x + lo.y * lo.y + hi.x * hi.x + hi.y * hi.y;
#pragma unroll
    for (int o = 16; o > 0; o >>= 1)
        ss += __shfl_xor_sync(0xffffffffu, ss, o);
    const float inv = rsqrtf(ss * (1.0f / HDIM) + EPSV) * oscale;

    const float g0 = (1.0f + scale[d])             * inv;
    const float g1 = (1.0f + scale[d + 1])         * inv;
    const float g2 = (1.0f + scale[d + HHALF])     * inv;
    const float g3 = (1.0f + scale[d + 1 + HHALF]) * inv;

    const float x1a = lo.x * g0, x1b = lo.y * g1;
    const float x2a = hi.x * g2, x2b = hi.y * g3;

    const float c0 = cs[(size_t)tt * HHALF + d];
    const float c1 = cs[(size_t)tt * HHALF + d + 1];
    const float s0 = sn[(size_t)tt * HHALF + d];
    const float s1 = sn[(size_t)tt * HHALF + d + 1];

    *(__half2*)&out[base + d] =
        __floats2half2_rn(x1a * c0 - x2a * s0, x1b * c1 - x2b * s1);
    *(__half2*)&out[base + d + HHALF] =
        __floats2half2_rn(x2a * c0 + x1a * s0, x2b * c1 + x1b * s1);
}

// ---------------------------------------------------------------------------
// Flash attention via mma.sync fp16 (register-Q, log2-domain scores).
// Epilogue writes fp16 hi/lo pair for the Wo split-GEMM.
// ---------------------------------------------------------------------------
constexpr int LDH  = 136;                  // halves per smem row (128+8)
constexpr int KSTG = 64 * LDH * 2;         // 17408 B (one K or V tile)
constexpr int FSTG = 2 * KSTG;             // 34816 B per stage
constexpr int FLASH_SMEM = 2 * FSTG;       // 69632 B

__global__ __launch_bounds__(256) void flash_mma(
    const __half* __restrict__ Qh, const __half* __restrict__ Kh,
    const __half* __restrict__ Vh,
    __half* __restrict__ Oh, __half* __restrict__ Ol)
{
    extern __shared__ __align__(16) char smf[];
    const uint32_t sb = smem_u32(smf);
    const int t = threadIdx.x, lane = t & 31, wid = t >> 5;
    const int qt = (SEQ / 128 - 1) - blockIdx.x;   // heavy tiles first
    const int h = blockIdx.y, b = blockIdx.z;
    const int q0 = qt * 128;
    const int kh = h >> 2;

    const __half* Qg = Qh + (size_t)(b * SEQ + q0) * DM + h * HDIM;
    const __half* Kg = Kh + (size_t)(b * SEQ) * KVD + kh * HDIM;
    const __half* Vg = Vh + (size_t)(b * SEQ) * KVD + kh * HDIM;

    // ---- Q tile -> smem -> register fragments (once)
    {
        const int row = t >> 1;
        const int cb  = (t & 1) * 8;
#pragma unroll
        for (int i = 0; i < 8; i++)
            cp16(sb + row * (LDH * 2) + (cb + i) * 16,
                 Qg + (size_t)row * DM + (size_t)(cb + i) * 8);
        cp_commit();
    }
    cp_wait<0>();
    __syncthreads();

    uint32_t qf[8][4];
    {
        const uint32_t a_off = sb + (wid * 16 + (lane & 15)) * (LDH * 2) +
                               ((lane >> 4) << 4);
#pragma unroll
        for (int ks = 0; ks < 8; ks++)
            ldsm4(qf[ks][0], qf[ks][1], qf[ks][2], qf[ks][3], a_off + ks * 32);
    }
    __syncthreads();   // Q smem region free

    float mrow[2] = {-1e30f, -1e30f};
    float lrow[2] = {0.0f, 0.0f};
    float o[16][4] = {};

    const int ntk = 2 * qt + 2;
    auto load_kv = [&](int kt, int s) {
        const int k0 = kt * 64;
        const int row = t >> 2;
        const uint32_t Kb = sb + s * FSTG;
        const uint32_t Vb = Kb + KSTG;
#pragma unroll
        for (int i = 0; i < 4; i++) {
            const int c = (t & 3) + i * 4;
            cp16(Kb + row * (LDH * 2) + c * 16,
                 Kg + (size_t)(k0 + row) * KVD + (size_t)c * 8);
            cp16(Vb + row * (LDH * 2) + c * 16,
                 Vg + (size_t)(k0 + row) * KVD + (size_t)c * 8);
        }
        cp_commit();
    };
    load_kv(0, 0);

    const int wrow_hi = q0 + wid * 16 + 15;
    const int myrow   = q0 + wid * 16 + (lane >> 2);

    for (int kt = 0; kt < ntk; kt++) {
        if (kt + 1 < ntk) { load_kv(kt + 1, (kt + 1) & 1); cp_wait<1>(); }
        else              { cp_wait<0>(); }
        __syncthreads();

        const int k0 = kt * 64;
        const bool active = (k0 <= wrow_hi);
        if (active) {
            const uint32_t Kb = sb + (kt & 1) * FSTG;
            const uint32_t Vb = Kb + KSTG;

            float sc[8][4] = {};
#pragma unroll
            for (int j = 0; j < 4; j++) {
                const uint32_t kb = Kb +
                    (j * 16 + ((lane >> 4) << 3) + (lane & 7)) * (LDH * 2) +
                    (((lane >> 3) & 1) << 4);
#pragma unroll
                for (int ks = 0; ks < 8; ks++) {
                    uint32_t r0, r1, r2, r3;
                    ldsm4(r0, r1, r2, r3, kb + ks * 32);
                    mma_fp16(sc[2 * j],     qf[ks], r0, r1);
                    mma_fp16(sc[2 * j + 1], qf[ks], r2, r3);
                }
            }

            float tmax[2] = {-1e30f, -1e30f};
            const bool diag = (k0 + 63 > q0 + wid * 16);
            if (diag) {
#pragma unroll
                for (int nt = 0; nt < 8; nt++) {
                    const int kc = k0 + nt * 8 + ((lane & 3) << 1);
#pragma unroll
                    for (int hf = 0; hf < 2; hf++) {
                        const int r = myrow + hf * 8;
                        float v0 = sc[nt][hf * 2];
                        float v1 = sc[nt][hf * 2 + 1];
                        if (kc     > r) v0 = -1e30f;
                        if (kc + 1 > r) v1 = -1e30f;
                        sc[nt][hf * 2]     = v0;
                        sc[nt][hf * 2 + 1] = v1;
                        tmax[hf] = fmaxf(tmax[hf], fmaxf(v0, v1));
                    }
                }
            } else {
#pragma unroll
                for (int nt = 0; nt < 8; nt++) {
                    tmax[0] = fmaxf(tmax[0], fmaxf(sc[nt][0], sc[nt][1]));
                    tmax[1] = fmaxf(tmax[1], fmaxf(sc[nt][2], sc[nt][3]));
                }
            }
#pragma unroll
            for (int off = 1; off <= 2; off <<= 1) {
                tmax[0] = fmaxf(tmax[0], __shfl_xor_sync(0xffffffffu, tmax[0], off));
                tmax[1] = fmaxf(tmax[1], __shfl_xor_sync(0xffffffffu, tmax[1], off));
            }
            const float mn0 = fmaxf(mrow[0], tmax[0]);
            const float mn1 = fmaxf(mrow[1], tmax[1]);
            const float al0 = ex2(mrow[0] - mn0);
            const float al1 = ex2(mrow[1] - mn1);
            mrow[0] = mn0; mrow[1] = mn1;

            float rs[2] = {0.0f, 0.0f};
            uint32_t pf[8][2];
#pragma unroll
            for (int nt = 0; nt < 8; nt++) {
                const float e0 = ex2(sc[nt][0] - mn0);
                const float e1 = ex2(sc[nt][1] - mn0);
                const float e2 = ex2(sc[nt][2] - mn1);
                const float e3 = ex2(sc[nt][3] - mn1);
                rs[0] += e0 + e1;
                rs[1] += e2 + e3;
                __half2 p0 = __floats2half2_rn(e0, e1);
                __half2 p1 = __floats2half2_rn(e2, e3);
                pf[nt][0] = *(uint32_t*)&p0;
                pf[nt][1] = *(uint32_t*)&p1;
            }
#pragma unroll
            for (int off = 1; off <= 2; off <<= 1) {
                rs[0] += __shfl_xor_sync(0xffffffffu, rs[0], off);
                rs[1] += __shfl_xor_sync(0xffffffffu, rs[1], off);
            }
            lrow[0] = lrow[0] * al0 + rs[0];
            lrow[1] = lrow[1] * al1 + rs[1];

#pragma unroll
            for (int nt = 0; nt < 16; nt++) {
                o[nt][0] *= al0; o[nt][1] *= al0;
                o[nt][2] *= al1; o[nt][3] *= al1;
            }

#pragma unroll
            for (int ks = 0; ks < 4; ks++) {
                uint32_t a[4] = {pf[2 * ks][0], pf[2 * ks][1],
                                 pf[2 * ks + 1][0], pf[2 * ks + 1][1]};
                const uint32_t vrow = Vb + (ks * 16 + (lane & 15)) * (LDH * 2) +
                                      (((lane >> 4) << 3) << 1);
#pragma unroll
                for (int vg = 0; vg < 8; vg++) {
                    uint32_t b0, b1, b2, b3;
                    ldsm4t(b0, b1, b2, b3, vrow + vg * 32);
                    mma_fp16(o[2 * vg],     a, b0, b1);
                    mma_fp16(o[2 * vg + 1], a, b2, b3);
                }
            }
        }
        __syncthreads();
    }

    const float inv0 = 1.0f / lrow[0];
    const float inv1 = 1.0f / lrow[1];
    const int colb = h * HDIM + ((lane & 3) << 1);
#pragma unroll
    for (int nt = 0; nt < 16; nt++) {
        const size_t i0 = (size_t)(b * SEQ + myrow) * DM + colb + nt * 8;
        const size_t i1 = i0 + (size_t)8 * DM;
        float x0 = o[nt][0] * inv0, x1 = o[nt][1] * inv0;
        float x2 = o[nt][2] * inv1, x3 = o[nt][3] * inv1;
        __half h0 = __float2half(x0), h1 = __float2half(x1);
        __half h2 = __float2half(x2), h3 = __float2half(x3);
        *(__half2*)&Oh[i0] = __halves2half2(h0, h1);
        *(__half2*)&Oh[i1] = __halves2half2(h2, h3);
        *(__half2*)&Ol[i0] = __halves2half2(
            __float2half(x0 - __half2float(h0)),
            __float2half(x1 - __half2float(h1)));
        *(__half2*)&Ol[i1] = __halves2half2(
            __float2half(x2 - __half2float(h2)),
            __float2half(x3 - __half2float(h3)));
    }
}

// ---------------------------------------------------------------------------
// Launch
// ---------------------------------------------------------------------------
extern "C" void kernel_launch(void* const* d_in, const int* in_sizes, int n_in,
                              void* d_out, int out_size)
{
    const float* q_input  = (const float*)d_in[0];
    const float* kv_input = (const float*)d_in[1];
    const float* cosb     = (const float*)d_in[3];
    const float* sinb     = (const float*)d_in[4];
    const float* Wq       = (const float*)d_in[5];
    const float* Wk       = (const float*)d_in[6];
    const float* Wv       = (const float*)d_in[7];
    const float* q_scale  = (const float*)d_in[8];
    const float* k_scale  = (const float*)d_in[9];
    const float* Wo       = (const float*)d_in[10];
    float* out = (float*)d_out;

    float *Qp, *Kp;
    __half *Qh, *Kh, *Vh;
    cudaGetSymbolAddress((void**)&Qp, g_Qp);
    cudaGetSymbolAddress((void**)&Kp, g_Kp);
    cudaGetSymbolAddress((void**)&Qh, g_Qh);
    cudaGetSymbolAddress((void**)&Kh, g_Kh);
    cudaGetSymbolAddress((void**)&Vh, g_Vh);

    __half *Aqh, *Aql, *Akh, *Akl, *Aoh, *Aol;
    __half *WqT, *WkvT, *WoT;
    cudaGetSymbolAddress((void**)&Aqh, g_Aq_h);
    cudaGetSymbolAddress((void**)&Aql, g_Aq_l);
    cudaGetSymbolAddress((void**)&Akh, g_Akv_h);
    cudaGetSymbolAddress((void**)&Akl, g_Akv_l);
    cudaGetSymbolAddress((void**)&Aoh, g_Ao_h);
    cudaGetSymbolAddress((void**)&Aol, g_Ao_l);
    cudaGetSymbolAddress((void**)&WqT, g_WqT);
    cudaGetSymbolAddress((void**)&WkvT, g_WkvT);
    cudaGetSymbolAddress((void**)&WoT, g_WoT);

    cudaFuncSetAttribute(gemm_wo, cudaFuncAttributeMaxDynamicSharedMemorySize,
                         GEMM_SMEM);
    cudaFuncSetAttribute(gemm_qkv, cudaFuncAttributeMaxDynamicSharedMemorySize,
                         GEMM_SMEM);
    cudaFuncSetAttribute(flash_mma, cudaFuncAttributeMaxDynamicSharedMemorySize,
                         FLASH_SMEM);

    dim3 blk(256);

    // zero the accumulated projection buffers
    zero_qkv<<<(ZTOT + 255) / 256, blk>>>(Qp, Kp, Vh);

    // activation fp16 hi/lo splits: both tensors in one launch
    split_rows2<<<(2 * (MR * DM / 4) + 255) / 256, blk>>>(
        q_input, Aqh, Aql, kv_input, Akh, Akl, MR * DM / 4);
    // weight transposes (fp16): all four in one launch
    split_transpose4<<<dim3(DM / 32, DM / 32, 4), dim3(32, 8)>>>(
        Wq, Wk, Wv, Wo, WqT, WkvT, WoT);

    // Merged Q + KV projections, 2-term section-split (768 CTAs x 64 iters)
    gemm_qkv<<<dim3(24, MR / 256, 2), blk, GEMM_SMEM>>>(
        Aqh, Aql, Akh, Akl, WqT, WkvT, Qp, Kp, Vh);

    // RMSNorm + RoPE for Q and K in one launch (Q pre-scaled to log2 domain)
    norm_rope_qk<<<(MR * (NH + NKV)) / 8, blk>>>(
        Qp, Kp, q_scale, k_scale, cosb, sinb, Qh, Kh);

    // Flash attention (fp16 tensor cores), writes fp16 hi/lo
    flash_mma<<<dim3(SEQ / 128, NH, BATCH), blk, FLASH_SMEM>>>(
        Qh, Kh, Vh, Aoh, Aol);

    // Output projection: 128-iter 2-term, fp32 into d_out
    gemm_wo<<<dim3(DM / 128, MR / 256), blk, GEMM_SMEM>>>(
        Aoh, Aol, WoT, out);
}

// round 17
// speedup vs baseline: 1.4629x; 1.4629x over previous
#include <cuda_runtime.h>
#include <cuda_bf16.h>
#include <cuda_fp16.h>
#include <math.h>
#include <stdint.h>

// Problem constants
constexpr int BATCH = 2;
constexpr int SEQ   = 2048;
constexpr int DM    = 2048;
constexpr int NH    = 16;
constexpr int NKV   = 4;
constexpr int HDIM  = 128;
constexpr int HHALF = 64;
constexpr float EPSV = 1e-6f;
constexpr float SCL_LOG2 = 0.12754245006483662f; // 1/sqrt(128) * log2(e)
constexpr int MR  = BATCH * SEQ;                  // 4096 rows
constexpr int KVD = NKV * HDIM;                   // 512

// ---------------- scratch (device globals — no runtime allocation) --------
__device__ float g_Qp[MR * DM];                   // Q projection fp32 (accumulated)
__device__ float g_Kp[MR * KVD];                  // K projection fp32 (accumulated)
__device__ __half g_Qh[MR * DM];                  // Q after norm+rope (pre-scaled), fp16
__device__ __half g_Kh[MR * KVD];                 // K after norm+rope, fp16
__device__ __half g_Vh[MR * KVD];                 // V projection, fp16 (accumulated)

__device__ __half g_Aq_h[MR * DM],  g_Aq_l[MR * DM];     // fp16 hi/lo activations
__device__ __half g_Akv_h[MR * DM], g_Akv_l[MR * DM];
__device__ __half g_Ao_h[MR * DM],  g_Ao_l[MR * DM];     // attn out hi/lo
__device__ __half g_WqT[DM * DM];                         // fp16 weights (transposed)
__device__ __half g_WkvT[2 * KVD * DM];                   // K rows 0-511, V rows 512-1023
__device__ __half g_WoT[DM * DM];

// ---------------------------------------------------------------------------
// Helpers (baseline PTX only: cp.async, ldmatrix, mma.sync)
// ---------------------------------------------------------------------------
__device__ __forceinline__ uint32_t smem_u32(const void* p) {
    uint32_t a;
    asm("{ .reg .u64 t; cvta.to.shared.u64 t, %1; cvt.u32.u64 %0, t; }"
        : "=r"(a) : "l"(p));
    return a;
}

__device__ __forceinline__ void cp16(uint32_t dst, const void* src) {
    asm volatile("cp.async.cg.shared.global [%0], [%1], 16;" :: "r"(dst), "l"(src));
}
__device__ __forceinline__ void cp_commit() {
    asm volatile("cp.async.commit_group;" ::: "memory");
}
template <int N>
__device__ __forceinline__ void cp_wait() {
    asm volatile("cp.async.wait_group %0;" :: "n"(N) : "memory");
}

__device__ __forceinline__ float ex2(float x) {
    float y;
    asm("ex2.approx.f32 %0, %1;" : "=f"(y) : "f"(x));
    return y;
}

__device__ __forceinline__ void ldsm4(uint32_t& r0, uint32_t& r1, uint32_t& r2,
                                      uint32_t& r3, uint32_t addr) {
    asm volatile("ldmatrix.sync.aligned.m8n8.x4.shared.b16 {%0,%1,%2,%3}, [%4];"
                 : "=r"(r0), "=r"(r1), "=r"(r2), "=r"(r3) : "r"(addr));
}
__device__ __forceinline__ void ldsm4t(uint32_t& r0, uint32_t& r1, uint32_t& r2,
                                       uint32_t& r3, uint32_t addr) {
    asm volatile("ldmatrix.sync.aligned.m8n8.x4.trans.shared.b16 {%0,%1,%2,%3}, [%4];"
                 : "=r"(r0), "=r"(r1), "=r"(r2), "=r"(r3) : "r"(addr));
}

__device__ __forceinline__ void mma_fp16(float* c, const uint32_t* a,
                                         uint32_t b0, uint32_t b1) {
    asm volatile(
        "mma.sync.aligned.m16n8k16.row.col.f32.f16.f16.f32 "
        "{%0,%1,%2,%3}, {%4,%5,%6,%7}, {%8,%9}, {%0,%1,%2,%3};"
        : "+f"(c[0]), "+f"(c[1]), "+f"(c[2]), "+f"(c[3])
        : "r"(a[0]), "r"(a[1]), "r"(a[2]), "r"(a[3]), "r"(b0), "r"(b1));
}

// ---------------------------------------------------------------------------
// Combined: fp16 hi/lo split of both activation tensors + zero-init of the
// accumulated projection buffers, one launch.
// Thread index ranges:
//   [0, n4)        : split q_input
//   [n4, 2n4)      : split kv_input
//   [2n4, 2n4+ZTOT): zero Qp/Kp/Vh (float4-wide)
// ---------------------------------------------------------------------------
constexpr int ZQ4 = MR * DM / 4;
constexpr int ZK4 = MR * KVD / 4;
constexpr int ZV4 = MR * KVD / 8;
constexpr int ZTOT = ZQ4 + ZK4 + ZV4;

__global__ __launch_bounds__(256) void split_zero(
    const float* __restrict__ X1, __half* __restrict__ H1, __half* __restrict__ L1,
    const float* __restrict__ X2, __half* __restrict__ H2, __half* __restrict__ L2,
    float* __restrict__ Qp, float* __restrict__ Kp, __half* __restrict__ Vh,
    int n4)
{
    int i = blockIdx.x * blockDim.x + threadIdx.x;
    if (i >= 2 * n4) {
        i -= 2 * n4;
        if (i >= ZTOT) return;
        const float4 z = make_float4(0.f, 0.f, 0.f, 0.f);
        if (i < ZQ4)            ((float4*)Qp)[i] = z;
        else if (i < ZQ4 + ZK4) ((float4*)Kp)[i - ZQ4] = z;
        else                    ((float4*)Vh)[i - ZQ4 - ZK4] = z;
        return;
    }
    const float* X;
    __half *Hh, *Ll;
    if (i < n4) { X = X1; Hh = H1; Ll = L1; }
    else        { X = X2; Hh = H2; Ll = L2; i -= n4; }

    float4 v = ((const float4*)X)[i];
    __half h0 = __float2half(v.x);
    __half h1 = __float2half(v.y);
    __half h2 = __float2half(v.z);
    __half h3 = __float2half(v.w);
    __half2* Hp = (__half2*)Hh;
    Hp[2 * i]     = __halves2half2(h0, h1);
    Hp[2 * i + 1] = __halves2half2(h2, h3);
    __half l0 = __float2half(v.x - __half2float(h0));
    __half l1 = __float2half(v.y - __half2float(h1));
    __half l2 = __float2half(v.z - __half2float(h2));
    __half l3 = __float2half(v.w - __half2float(h3));
    __half2* Lp = (__half2*)Ll;
    Lp[2 * i]     = __halves2half2(l0, l1);
    Lp[2 * i + 1] = __halves2half2(l2, l3);
}

// ---------------------------------------------------------------------------
// Transpose to fp16 for ALL FOUR weights in one launch.
// ---------------------------------------------------------------------------
__global__ __launch_bounds__(256) void split_transpose4(
    const float* __restrict__ Wq, const float* __restrict__ Wk,
    const float* __restrict__ Wv, const float* __restrict__ Wo,
    __half* __restrict__ WqT, __half* __restrict__ WkvT, __half* __restrict__ WoT)
{
    const int z = blockIdx.z;
    const float* W;
    __half* TH;
    int N;
    if (z == 0)      { W = Wq; TH = WqT; N = DM; }
    else if (z == 1) { W = Wk; TH = WkvT; N = KVD; }
    else if (z == 2) { W = Wv; TH = WkvT + (size_t)KVD * DM; N = KVD; }
    else             { W = Wo; TH = WoT; N = DM; }

    const int n0 = blockIdx.y * 32;
    if (n0 >= N) return;
    const int k0 = blockIdx.x * 32;

    __shared__ float tile[32][33];
    const int tx = threadIdx.x, ty = threadIdx.y;     // 32 x 8
#pragma unroll
    for (int i = 0; i < 4; i++)
        tile[ty + i * 8][tx] = W[(size_t)(k0 + ty + i * 8) * N + n0 + tx];
    __syncthreads();
#pragma unroll
    for (int i = 0; i < 4; i++) {
        float v = tile[tx][ty + i * 8];
        int n = n0 + ty + i * 8;
        TH[(size_t)n * DM + k0 + tx] = __float2half(v);
    }
}

// ---------------------------------------------------------------------------
// GEMM tile configuration (round-15 validated optimum)
// CTA 128x128, BK=64, 8 warps (2x4), warp tile 64x32, 3-stage cp.async,
// 2 CTAs/SM.
// ---------------------------------------------------------------------------
constexpr int LDT    = 72;
constexpr int ABYTES = 128 * LDT * 2;      // 18432 B
constexpr int STAGEB = 2 * ABYTES;         // 36864 B
constexpr int NSTG   = 3;
constexpr int GEMM_SMEM = NSTG * STAGEB;   // 110592 B (2 CTAs/SM)

// 3-stage pipelined mainloop; A source switches A0 -> A1 at iteration 32.
template <int NIT>
__device__ __forceinline__ void gemm_mainloop2A(
    uint32_t sb,
    const __half* __restrict__ A0, const __half* __restrict__ A1,
    const __half* __restrict__ Bg,
    int m0, int n0, float (&acc)[4][4][4])
{
    const int t = threadIdx.x, lane = t & 31, wid = t >> 5;
    const int wm = wid & 1, wn = wid >> 1;

    const int lrow = t >> 3;
    const int lch  = t & 7;

    auto load_stage = [&](int it, int s) {
        const __half* Ag = (it < 32) ? A0 : A1;
        const int koff = (it & 31) << 6;
        const uint32_t Ab = sb + s * STAGEB;
        const uint32_t Bb = Ab + ABYTES;
#pragma unroll
        for (int i = 0; i < 4; i++) {
            const int row = lrow + i * 32;
            cp16(Ab + row * (LDT * 2) + lch * 16,
                 Ag + (size_t)(m0 + row) * DM + koff + lch * 8);
            cp16(Bb + row * (LDT * 2) + lch * 16,
                 Bg + (size_t)(n0 + row) * DM + koff + lch * 8);
        }
        cp_commit();
    };

    load_stage(0, 0);
    load_stage(1, 1);

    const uint32_t a_off = (uint32_t)((wm * 64 + (lane & 15)) * (LDT * 2) +
                                      ((lane >> 4) << 4));
    const uint32_t b_off = (uint32_t)((wn * 32 + ((lane >> 4) << 3) + (lane & 7)) * (LDT * 2) +
                                      (((lane >> 3) & 1) << 4));

    int stg = 0;
    for (int it = 0; it < NIT; it++) {
        cp_wait<1>();
        __syncthreads();

        if (it + 2 < NIT) {
            const int s2 = (stg + 2 >= NSTG) ? stg + 2 - NSTG : stg + 2;
            load_stage(it + 2, s2);
        } else {
            cp_commit();
        }

        const uint32_t Ab = sb + stg * STAGEB;
        const uint32_t Bb = Ab + ABYTES;

#pragma unroll
        for (int ks = 0; ks < 4; ks++) {
            uint32_t a[4][4];
            uint32_t b[4][2];
#pragma unroll
            for (int i = 0; i < 4; i++)
                ldsm4(a[i][0], a[i][1], a[i][2], a[i][3],
                      Ab + a_off + i * 16 * (LDT * 2) + ks * 32);
#pragma unroll
            for (int j = 0; j < 2; j++) {
                uint32_t r0, r1, r2, r3;
                ldsm4(r0, r1, r2, r3,
                      Bb + b_off + j * 16 * (LDT * 2) + ks * 32);
                b[j * 2][0] = r0;     b[j * 2][1] = r1;
                b[j * 2 + 1][0] = r2; b[j * 2 + 1][1] = r3;
            }
#pragma unroll
            for (int i = 0; i < 4; i++)
#pragma unroll
                for (int j = 0; j < 4; j++)
                    mma_fp16(acc[i][j], a[i], b[j][0], b[j][1]);
        }

        stg = (stg + 1 >= NSTG) ? 0 : stg + 1;
    }
}

// Wo projection: 64 iters (Ah then Al), plain fp32 out.
__global__ __launch_bounds__(256, 2) void gemm_wo(
    const __half* __restrict__ Ahi, const __half* __restrict__ Alo,
    const __half* __restrict__ Bg, float* __restrict__ Cf)
{
    extern __shared__ __align__(16) char smg[];
    const int m0 = blockIdx.y * 128, n0 = blockIdx.x * 128;
    float acc[4][4][4] = {};
    gemm_mainloop2A<64>(smem_u32(smg), Ahi, Alo, Bg, m0, n0, acc);

    const int lane = threadIdx.x & 31, wid = threadIdx.x >> 5;
    const int wm = wid & 1, wn = wid >> 1;
#pragma unroll
    for (int i = 0; i < 4; i++) {
#pragma unroll
        for (int j = 0; j < 4; j++) {
            const int m = m0 + wm * 64 + i * 16 + (lane >> 2);
            const int n = n0 + wn * 32 + j * 8 + ((lane & 3) << 1);
            *(float2*)&Cf[(size_t)m * DM + n] =
                make_float2(acc[i][j][0], acc[i][j][1]);
            *(float2*)&Cf[(size_t)(m + 8) * DM + n] =
                make_float2(acc[i][j][2], acc[i][j][3]);
        }
    }
}

// Merged Q + KV projections, section-split (blockIdx.z = 0: Ah, 1: Al),
// 32 iters/CTA, accumulated into pre-zeroed outputs with atomics.
__global__ __launch_bounds__(256, 2) void gemm_qkv(
    const __half* __restrict__ Aqh, const __half* __restrict__ Aql,
    const __half* __restrict__ Akh, const __half* __restrict__ Akl,
    const __half* __restrict__ WqT, const __half* __restrict__ WkvT,
    float* __restrict__ Qp, float* __restrict__ Kp, __half* __restrict__ Vh)
{
    extern __shared__ __align__(16) char smg[];
    const bool isQ = (blockIdx.x < 16);
    const int n0 = (isQ ? blockIdx.x : blockIdx.x - 16) * 128;
    const int m0 = blockIdx.y * 128;
    const int sec = blockIdx.z;                    // 0: Ah*W, 1: Al*W

    const __half* Ag = (sec == 1) ? (isQ ? Aql : Akl) : (isQ ? Aqh : Akh);
    const __half* Bg = isQ ? WqT : WkvT;

    float acc[4][4][4] = {};
    gemm_mainloop2A<32>(smem_u32(smg), Ag, Ag, Bg, m0, n0, acc);

    const int lane = threadIdx.x & 31, wid = threadIdx.x >> 5;
    const int wm = wid & 1, wn = wid >> 1;
    const bool isV = (!isQ) && (n0 >= KVD);

    if (!isV) {
        float* C = isQ ? Qp : Kp;
        const int W = isQ ? DM : KVD;
#pragma unroll
        for (int i = 0; i < 4; i++) {
#pragma unroll
            for (int j = 0; j < 4; j++) {
                const int m = m0 + wm * 64 + i * 16 + (lane >> 2);
                const int n = n0 + wn * 32 + j * 8 + ((lane & 3) << 1);
                atomicAdd(&C[(size_t)m * W + n],       acc[i][j][0]);
                atomicAdd(&C[(size_t)m * W + n + 1],   acc[i][j][1]);
                atomicAdd(&C[(size_t)(m + 8) * W + n],     acc[i][j][2]);
                atomicAdd(&C[(size_t)(m + 8) * W + n + 1], acc[i][j][3]);
            }
        }
    } else {
        const int nb = n0 - KVD;
#pragma unroll
        for (int i = 0; i < 4; i++) {
#pragma unroll
            for (int j = 0; j < 4; j++) {
                const int m = m0 + wm * 64 + i * 16 + (lane >> 2);
                const int n = nb + wn * 32 + j * 8 + ((lane & 3) << 1);
                atomicAdd((__half2*)&Vh[(size_t)m * KVD + n],
                          __floats2half2_rn(acc[i][j][0], acc[i][j][1]));
                atomicAdd((__half2*)&Vh[(size_t)(m + 8) * KVD + n],
                          __floats2half2_rn(acc[i][j][2], acc[i][j][3]));
            }
        }
    }
}

// ---------------------------------------------------------------------------
// Fused per-head RMSNorm + RoPE for BOTH Q and K in one launch.
// Q output pre-scaled by SM_SCALE*log2(e).
// ---------------------------------------------------------------------------
__global__ __launch_bounds__(256) void norm_rope_qk(
    const float* __restrict__ Qp, const float* __restrict__ Kp,
    const float* __restrict__ q_scale, const float* __restrict__ k_scale,
    const float* __restrict__ cs, const float* __restrict__ sn,
    __half* __restrict__ Qh, __half* __restrict__ Kh)
{
    int gw   = (int)((blockIdx.x * blockDim.x + threadIdx.x) >> 5);
    const int lane = threadIdx.x & 31;

    const float* P;
    const float* scale;
    __half* out;
    int nh;
    float oscale;
    if (gw < MR * NH) {
        P = Qp; scale = q_scale; out = Qh; nh = NH; oscale = SCL_LOG2;
    } else {
        gw -= MR * NH;
        P = Kp; scale = k_scale; out = Kh; nh = NKV; oscale = 1.0f;
    }

    const int h  = gw % nh;
    const int bt = gw / nh;
    const int tt = bt % SEQ;

    const size_t base = (size_t)bt * (nh * HDIM) + (size_t)h * HDIM;
    const int d = lane * 2;

    float2 lo = *(const float2*)&P[base + d];
    float2 hi = *(const float2*)&P[base + d + HHALF];

    float ss = lo.x * lo.x + lo.y * lo.y + hi.x * hi.x + hi.y * hi.y;
#pragma unroll
    for (int o = 16; o > 0; o >>= 1)
        ss += __shfl_xor_sync(0xffffffffu, ss, o);
    const float inv = rsqrtf(ss * (1.0f / HDIM) + EPSV) * oscale;

    const float g0 = (1.0f + scale[d])             * inv;
    const float g1 = (1.0f + scale[d + 1])         * inv;
    const float g2 = (1.0f + scale[d + HHALF])     * inv;
    const float g3 = (1.0f + scale[d + 1 + HHALF]) * inv;

    const float x1a = lo.x * g0, x1b = lo.y * g1;
    const float x2a = hi.x * g2, x2b = hi.y * g3;

    const float c0 = cs[(size_t)tt * HHALF + d];
    const float c1 = cs[(size_t)tt * HHALF + d + 1];
    const float s0 = sn[(size_t)tt * HHALF + d];
    const float s1 = sn[(size_t)tt * HHALF + d + 1];

    *(__half2*)&out[base + d] =
        __floats2half2_rn(x1a * c0 - x2a * s0, x1b * c1 - x2b * s1);
    *(__half2*)&out[base + d + HHALF] =
        __floats2half2_rn(x2a * c0 + x1a * s0, x2b * c1 + x1b * s1);
}

// ---------------------------------------------------------------------------
// Flash attention via mma.sync fp16 (register-Q, log2-domain scores).
// Epilogue writes fp16 hi/lo pair for the Wo split-GEMM.
// ---------------------------------------------------------------------------
constexpr int LDH  = 136;                  // halves per smem row (128+8)
constexpr int KSTG = 64 * LDH * 2;         // 17408 B (one K or V tile)
constexpr int FSTG = 2 * KSTG;             // 34816 B per stage
constexpr int FLASH_SMEM = 2 * FSTG;       // 69632 B

__global__ __launch_bounds__(256) void flash_mma(
    const __half* __restrict__ Qh, const __half* __restrict__ Kh,
    const __half* __restrict__ Vh,
    __half* __restrict__ Oh, __half* __restrict__ Ol)
{
    extern __shared__ __align__(16) char smf[];
    const uint32_t sb = smem_u32(smf);
    const int t = threadIdx.x, lane = t & 31, wid = t >> 5;
    const int qt = (SEQ / 128 - 1) - blockIdx.x;   // heavy tiles first
    const int h = blockIdx.y, b = blockIdx.z;
    const int q0 = qt * 128;
    const int kh = h >> 2;

    const __half* Qg = Qh + (size_t)(b * SEQ + q0) * DM + h * HDIM;
    const __half* Kg = Kh + (size_t)(b * SEQ) * KVD + kh * HDIM;
    const __half* Vg = Vh + (size_t)(b * SEQ) * KVD + kh * HDIM;

    // ---- Q tile -> smem -> register fragments (once)
    {
        const int row = t >> 1;
        const int cb  = (t & 1) * 8;
#pragma unroll
        for (int i = 0; i < 8; i++)
            cp16(sb + row * (LDH * 2) + (cb + i) * 16,
                 Qg + (size_t)row * DM + (size_t)(cb + i) * 8);
        cp_commit();
    }
    cp_wait<0>();
    __syncthreads();

    uint32_t qf[8][4];
    {
        const uint32_t a_off = sb + (wid * 16 + (lane & 15)) * (LDH * 2) +
                               ((lane >> 4) << 4);
#pragma unroll
        for (int ks = 0; ks < 8; ks++)
            ldsm4(qf[ks][0], qf[ks][1], qf[ks][2], qf[ks][3], a_off + ks * 32);
    }
    __syncthreads();   // Q smem region free

    float mrow[2] = {-1e30f, -1e30f};
    float lrow[2] = {0.0f, 0.0f};
    float o[16][4] = {};

    const int ntk = 2 * qt + 2;
    auto load_kv = [&](int kt, int s) {
        const int k0 = kt * 64;
        const int row = t >> 2;
        const uint32_t Kb = sb + s * FSTG;
        const uint32_t Vb = Kb + KSTG;
#pragma unroll
        for (int i = 0; i < 4; i++) {
            const int c = (t & 3) + i * 4;
            cp16(Kb + row * (LDH * 2) + c * 16,
                 Kg + (size_t)(k0 + row) * KVD + (size_t)c * 8);
            cp16(Vb + row * (LDH * 2) + c * 16,
                 Vg + (size_t)(k0 + row) * KVD + (size_t)c * 8);
        }
        cp_commit();
    };
    load_kv(0, 0);

    const int wrow_hi = q0 + wid * 16 + 15;
    const int myrow   = q0 + wid * 16 + (lane >> 2);

    for (int kt = 0; kt < ntk; kt++) {
        if (kt + 1 < ntk) { load_kv(kt + 1, (kt + 1) & 1); cp_wait<1>(); }
        else              { cp_wait<0>(); }
        __syncthreads();

        const int k0 = kt * 64;
        const bool active = (k0 <= wrow_hi);
        if (active) {
            const uint32_t Kb = sb + (kt & 1) * FSTG;
            const uint32_t Vb = Kb + KSTG;

            float sc[8][4] = {};
#pragma unroll
            for (int j = 0; j < 4; j++) {
                const uint32_t kb = Kb +
                    (j * 16 + ((lane >> 4) << 3) + (lane & 7)) * (LDH * 2) +
                    (((lane >> 3) & 1) << 4);
#pragma unroll
                for (int ks = 0; ks < 8; ks++) {
                    uint32_t r0, r1, r2, r3;
                    ldsm4(r0, r1, r2, r3, kb + ks * 32);
                    mma_fp16(sc[2 * j],     qf[ks], r0, r1);
                    mma_fp16(sc[2 * j + 1], qf[ks], r2, r3);
                }
            }

            float tmax[2] = {-1e30f, -1e30f};
            const bool diag = (k0 + 63 > q0 + wid * 16);
            if (diag) {
#pragma unroll
                for (int nt = 0; nt < 8; nt++) {
                    const int kc = k0 + nt * 8 + ((lane & 3) << 1);
#pragma unroll
                    for (int hf = 0; hf < 2; hf++) {
                        const int r = myrow + hf * 8;
                        float v0 = sc[nt][hf * 2];
                        float v1 = sc[nt][hf * 2 + 1];
                        if (kc     > r) v0 = -1e30f;
                        if (kc + 1 > r) v1 = -1e30f;
                        sc[nt][hf * 2]     = v0;
                        sc[nt][hf * 2 + 1] = v1;
                        tmax[hf] = fmaxf(tmax[hf], fmaxf(v0, v1));
                    }
                }
            } else {
#pragma unroll
                for (int nt = 0; nt < 8; nt++) {
                    tmax[0] = fmaxf(tmax[0], fmaxf(sc[nt][0], sc[nt][1]));
                    tmax[1] = fmaxf(tmax[1], fmaxf(sc[nt][2], sc[nt][3]));
                }
            }
#pragma unroll
            for (int off = 1; off <= 2; off <<= 1) {
                tmax[0] = fmaxf(tmax[0], __shfl_xor_sync(0xffffffffu, tmax[0], off));
                tmax[1] = fmaxf(tmax[1], __shfl_xor_sync(0xffffffffu, tmax[1], off));
            }
            const float mn0 = fmaxf(mrow[0], tmax[0]);
            const float mn1 = fmaxf(mrow[1], tmax[1]);
            const float al0 = ex2(mrow[0] - mn0);
            const float al1 = ex2(mrow[1] - mn1);
            mrow[0] = mn0; mrow[1] = mn1;

            float rs[2] = {0.0f, 0.0f};
            uint32_t pf[8][2];
#pragma unroll
            for (int nt = 0; nt < 8; nt++) {
                const float e0 = ex2(sc[nt][0] - mn0);
                const float e1 = ex2(sc[nt][1] - mn0);
                const float e2 = ex2(sc[nt][2] - mn1);
                const float e3 = ex2(sc[nt][3] - mn1);
                rs[0] += e0 + e1;
                rs[1] += e2 + e3;
                __half2 p0 = __floats2half2_rn(e0, e1);
                __half2 p1 = __floats2half2_rn(e2, e3);
                pf[nt][0] = *(uint32_t*)&p0;
                pf[nt][1] = *(uint32_t*)&p1;
            }
#pragma unroll
            for (int off = 1; off <= 2; off <<= 1) {
                rs[0] += __shfl_xor_sync(0xffffffffu, rs[0], off);
                rs[1] += __shfl_xor_sync(0xffffffffu, rs[1], off);
            }
            lrow[0] = lrow[0] * al0 + rs[0];
            lrow[1] = lrow[1] * al1 + rs[1];

#pragma unroll
            for (int nt = 0; nt < 16; nt++) {
                o[nt][0] *= al0; o[nt][1] *= al0;
                o[nt][2] *= al1; o[nt][3] *= al1;
            }

#pragma unroll
            for (int ks = 0; ks < 4; ks++) {
                uint32_t a[4] = {pf[2 * ks][0], pf[2 * ks][1],
                                 pf[2 * ks + 1][0], pf[2 * ks + 1][1]};
                const uint32_t vrow = Vb + (ks * 16 + (lane & 15)) * (LDH * 2) +
                                      (((lane >> 4) << 3) << 1);
#pragma unroll
                for (int vg = 0; vg < 8; vg++) {
                    uint32_t b0, b1, b2, b3;
                    ldsm4t(b0, b1, b2, b3, vrow + vg * 32);
                    mma_fp16(o[2 * vg],     a, b0, b1);
                    mma_fp16(o[2 * vg + 1], a, b2, b3);
                }
            }
        }
        __syncthreads();
    }

    const float inv0 = 1.0f / lrow[0];
    const float inv1 = 1.0f / lrow[1];
    const int colb = h * HDIM + ((lane & 3) << 1);
#pragma unroll
    for (int nt = 0; nt < 16; nt++) {
        const size_t i0 = (size_t)(b * SEQ + myrow) * DM + colb + nt * 8;
        const size_t i1 = i0 + (size_t)8 * DM;
        float x0 = o[nt][0] * inv0, x1 = o[nt][1] * inv0;
        float x2 = o[nt][2] * inv1, x3 = o[nt][3] * inv1;
        __half h0 = __float2half(x0), h1 = __float2half(x1);
        __half h2 = __float2half(x2), h3 = __float2half(x3);
        *(__half2*)&Oh[i0] = __halves2half2(h0, h1);
        *(__half2*)&Oh[i1] = __halves2half2(h2, h3);
        *(__half2*)&Ol[i0] = __halves2half2(
            __float2half(x0 - __half2float(h0)),
            __float2half(x1 - __half2float(h1)));
        *(__half2*)&Ol[i1] = __halves2half2(
            __float2half(x2 - __half2float(h2)),
            __float2half(x3 - __half2float(h3)));
    }
}

// ---------------------------------------------------------------------------
// Launch
// ---------------------------------------------------------------------------
extern "C" void kernel_launch(void* const* d_in, const int* in_sizes, int n_in,
                              void* d_out, int out_size)
{
    const float* q_input  = (const float*)d_in[0];
    const float* kv_input = (const float*)d_in[1];
    const float* cosb     = (const float*)d_in[3];
    const float* sinb     = (const float*)d_in[4];
    const float* Wq       = (const float*)d_in[5];
    const float* Wk       = (const float*)d_in[6];
    const float* Wv       = (const float*)d_in[7];
    const float* q_scale  = (const float*)d_in[8];
    const float* k_scale  = (const float*)d_in[9];
    const float* Wo       = (const float*)d_in[10];
    float* out = (float*)d_out;

    float *Qp, *Kp;
    __half *Qh, *Kh, *Vh;
    cudaGetSymbolAddress((void**)&Qp, g_Qp);
    cudaGetSymbolAddress((void**)&Kp, g_Kp);
    cudaGetSymbolAddress((void**)&Qh, g_Qh);
    cudaGetSymbolAddress((void**)&Kh, g_Kh);
    cudaGetSymbolAddress((void**)&Vh, g_Vh);

    __half *Aqh, *Aql, *Akh, *Akl, *Aoh, *Aol;
    __half *WqT, *WkvT, *WoT;
    cudaGetSymbolAddress((void**)&Aqh, g_Aq_h);
    cudaGetSymbolAddress((void**)&Aql, g_Aq_l);
    cudaGetSymbolAddress((void**)&Akh, g_Akv_h);
    cudaGetSymbolAddress((void**)&Akl, g_Akv_l);
    cudaGetSymbolAddress((void**)&Aoh, g_Ao_h);
    cudaGetSymbolAddress((void**)&Aol, g_Ao_l);
    cudaGetSymbolAddress((void**)&WqT, g_WqT);
    cudaGetSymbolAddress((void**)&WkvT, g_WkvT);
    cudaGetSymbolAddress((void**)&WoT, g_WoT);

    cudaFuncSetAttribute(gemm_wo, cudaFuncAttributeMaxDynamicSharedMemorySize,
                         GEMM_SMEM);
    cudaFuncSetAttribute(gemm_qkv, cudaFuncAttributeMaxDynamicSharedMemorySize,
                         GEMM_SMEM);
    cudaFuncSetAttribute(flash_mma, cudaFuncAttributeMaxDynamicSharedMemorySize,
                         FLASH_SMEM);

    dim3 blk(256);

    // activation fp16 hi/lo splits + zero-init of accumulation buffers
    const int n4 = MR * DM / 4;
    split_zero<<<(2 * n4 + ZTOT + 255) / 256, blk>>>(
        q_input, Aqh, Aql, kv_input, Akh, Akl, Qp, Kp, Vh, n4);
    // weight transposes (fp16): all four in one launch
    split_transpose4<<<dim3(DM / 32, DM / 32, 4), dim3(32, 8)>>>(
        Wq, Wk, Wv, Wo, WqT, WkvT, WoT);

    // Merged Q + KV projections, 2-term section-split (1536 CTAs x 32 iters)
    gemm_qkv<<<dim3(24, MR / 128, 2), blk, GEMM_SMEM>>>(
        Aqh, Aql, Akh, Akl, WqT, WkvT, Qp, Kp, Vh);

    // RMSNorm + RoPE for Q and K in one launch (Q pre-scaled to log2 domain)
    norm_rope_qk<<<(MR * (NH + NKV)) / 8, blk>>>(
        Qp, Kp, q_scale, k_scale, cosb, sinb, Qh, Kh);

    // Flash attention (fp16 tensor cores), writes fp16 hi/lo
    flash_mma<<<dim3(SEQ / 128, NH, BATCH), blk, FLASH_SMEM>>>(
        Qh, Kh, Vh, Aoh, Aol);

    // Output projection: 64-iter 2-term, fp32 into d_out
    gemm_wo<<<dim3(DM / 128, MR / 128), blk, GEMM_SMEM>>>(
        Aoh, Aol, WoT, out);
}